// round 3
// baseline (speedup 1.0000x reference)
#include <cuda_runtime.h>
#include <cstdint>

#define NB 4
#define NA (1 << 20)
#define BPB 128                       // blocks per batch
#define NBLOCKS (NB * BPB)            // 512  (power of 2; <= 592 resident capacity)
#define NTHREADS 256
#define ROWS_PER_BLOCK (NA / BPB)     // 8192 rows per block
#define QUADS_PER_THREAD (ROWS_PER_BLOCK / 4 / NTHREADS)  // 8
#define CAND_CAP 32

// scratch: per block, 4 u64 keys: [col0_top1, col0_top2, col1_top1, col1_top2]
__device__ unsigned long long g_scratch[NBLOCKS * 4];
__device__ unsigned int g_count = 0;    // monotonic across graph replays
__device__ unsigned int g_release = 0;  // monotonic across graph replays

__device__ __forceinline__ unsigned long long make_key(float v, unsigned int idx) {
    // high 32: float bits of positive score (order-preserving)
    // low 32 : ~idx  (ties in score -> smaller index = larger key)
    return (((unsigned long long)__float_as_uint(v)) << 32) | (unsigned long long)(~idx);
}

__device__ __forceinline__ void upd2(unsigned long long& a1, unsigned long long& a2,
                                     unsigned long long k) {
    if (k > a1) { a2 = a1; a1 = k; }
    else if (k > a2) { a2 = k; }
}

// merge top-2 key list (b1>=b2) into (a1>=a2)
__device__ __forceinline__ void merge2(unsigned long long& a1, unsigned long long& a2,
                                       unsigned long long b1, unsigned long long b2) {
    unsigned long long hi = a1 > b1 ? a1 : b1;
    unsigned long long lo = a1 > b1 ? b1 : a1;
    unsigned long long m2 = a2 > b2 ? a2 : b2;
    a1 = hi;
    a2 = lo > m2 ? lo : m2;
}

// value-only: merge candidate top-2 (m1>=m2) into accumulator (a1>=a2)
__device__ __forceinline__ void merge2v(float& a1, float& a2, float m1, float m2) {
    float na2 = fmaxf(fminf(a1, m1), fmaxf(a2, m2));
    a1 = fmaxf(a1, m1);
    a2 = na2;
}

__global__ void __launch_bounds__(NTHREADS, 4)
fused_top2_decode(const float* __restrict__ probs,
                  const float* __restrict__ anchors,
                  const float* __restrict__ deltas,
                  const int* __restrict__ batch_ixs,
                  float* __restrict__ out) {
    const int tid = threadIdx.x;
    unsigned int epoch0 = 0;
    if (tid == 0) epoch0 = *(volatile unsigned int*)&g_release;  // pre-tail epoch

    const int blk   = blockIdx.x;
    const int batch = blk >> 7;          // / BPB
    const int chunk = blk & (BPB - 1);
    const long long row0 = (long long)batch * NA + (long long)chunk * ROWS_PER_BLOCK;
    const float4* __restrict__ p4 = reinterpret_cast<const float4*>(probs);

    // ---- value-only top-2 scan (3 FMNMX-class ops per element) ----
    float a1c0 = 0.f, a2c0 = 0.f;   // class column 0 (cls=1)
    float a1c1 = 0.f, a2c1 = 0.f;   // class column 1 (cls=2)

#pragma unroll
    for (int it = 0; it < QUADS_PER_THREAD; ++it) {
        const long long row = row0 + (long long)(it * NTHREADS + tid) * 4;
        const long long f4  = (row >> 2) * 3;
        const float4 A = p4[f4];
        const float4 B = p4[f4 + 1];
        const float4 C = p4[f4 + 2];
        // col0 elements: A.y, B.x, B.w, C.z ; col1: A.z, B.y, C.x, C.w
        {
            float h0 = fmaxf(A.y, B.x), l0 = fminf(A.y, B.x);
            float h1 = fmaxf(B.w, C.z), l1 = fminf(B.w, C.z);
            float m1 = fmaxf(h0, h1);
            float m2 = fmaxf(fminf(h0, h1), fmaxf(l0, l1));
            merge2v(a1c0, a2c0, m1, m2);
        }
        {
            float h0 = fmaxf(A.z, B.y), l0 = fminf(A.z, B.y);
            float h1 = fmaxf(C.x, C.w), l1 = fminf(C.x, C.w);
            float m1 = fmaxf(h0, h1);
            float m2 = fmaxf(fminf(h0, h1), fmaxf(l0, l1));
            merge2v(a1c1, a2c1, m1, m2);
        }
    }

    // ---- block value reduction ----
    __shared__ float4 sv[NTHREADS];
    __shared__ unsigned int scnt[2];
    __shared__ unsigned long long candk[2][CAND_CAP * 2];
    if (tid < 2) scnt[tid] = 0;
    sv[tid] = make_float4(a1c0, a2c0, a1c1, a2c1);
    __syncthreads();
    for (int off = NTHREADS / 2; off > 0; off >>= 1) {
        if (tid < off) {
            float4 a = sv[tid], b = sv[tid + off];
            merge2v(a.x, a.y, b.x, b.y);
            merge2v(a.z, a.w, b.z, b.w);
            sv[tid] = a;
        }
        __syncthreads();
    }
    const float4 bv = sv[0];   // {bv1c0, bv2c0, bv1c1, bv2c1}

    // ---- rare exact recovery: threads that might hold a block-top-2 element ----
    const bool cand0 = (a1c0 >= bv.y);
    const bool cand1 = (a1c1 >= bv.w);
    if (cand0 || cand1) {
        unsigned long long k0a = 0, k0b = 0, k1a = 0, k1b = 0;
#pragma unroll
        for (int it = 0; it < QUADS_PER_THREAD; ++it) {
            const long long row = row0 + (long long)(it * NTHREADS + tid) * 4;
            const long long f4  = (row >> 2) * 3;
            const float4 A = p4[f4];
            const float4 B = p4[f4 + 1];
            const float4 C = p4[f4 + 2];
            const unsigned int i0 = (unsigned int)(row * 2);
            if (cand0) {
                upd2(k0a, k0b, make_key(A.y, i0 + 0));
                upd2(k0a, k0b, make_key(B.x, i0 + 2));
                upd2(k0a, k0b, make_key(B.w, i0 + 4));
                upd2(k0a, k0b, make_key(C.z, i0 + 6));
            }
            if (cand1) {
                upd2(k1a, k1b, make_key(A.z, i0 + 1));
                upd2(k1a, k1b, make_key(B.y, i0 + 3));
                upd2(k1a, k1b, make_key(C.x, i0 + 5));
                upd2(k1a, k1b, make_key(C.w, i0 + 7));
            }
        }
        if (cand0) {
            unsigned int slot = atomicAdd(&scnt[0], 1u);
            if (slot < CAND_CAP) { candk[0][2 * slot] = k0a; candk[0][2 * slot + 1] = k0b; }
        }
        if (cand1) {
            unsigned int slot = atomicAdd(&scnt[1], 1u);
            if (slot < CAND_CAP) { candk[1][2 * slot] = k1a; candk[1][2 * slot + 1] = k1b; }
        }
    }
    __syncthreads();

    if (tid < 2) {
        const int n = min(scnt[tid], (unsigned int)CAND_CAP);
        unsigned long long b1 = 0, b2 = 0;
        for (int i = 0; i < 2 * n; ++i) upd2(b1, b2, candk[tid][i]);
        g_scratch[blk * 4 + tid * 2]     = b1;
        g_scratch[blk * 4 + tid * 2 + 1] = b2;
    }

    // ---- last-block election (monotonic, graph-replay safe) ----
    __shared__ bool isLast;
    __threadfence();
    __syncthreads();
    if (tid == 0) {
        unsigned int old = atomicAdd(&g_count, 1u);
        isLast = (((old + 1) & (NBLOCKS - 1)) == 0);
    }
    __syncthreads();
    if (!isLast) {
        // stay resident so the chip never enters the low-grid regime while
        // the last block runs the tail
        if (tid == 0) {
            while (*(volatile unsigned int*)&g_release == epoch0) __nanosleep(256);
        }
        return;
    }
    __threadfence();

    // ---- final reduction: 8 warps, one per (batch, class) group ----
    __shared__ unsigned long long gtop[16];
    __shared__ unsigned long long sorted16[16];
    const int warp = tid >> 5;
    const int lane = tid & 31;
    {
        const int gbatch = warp >> 1;
        const int col    = warp & 1;
        unsigned long long a1 = 0, a2 = 0;
        for (int b = lane; b < BPB; b += 32) {
            const int sblk = gbatch * BPB + b;
            merge2(a1, a2, g_scratch[sblk * 4 + col * 2], g_scratch[sblk * 4 + col * 2 + 1]);
        }
#pragma unroll
        for (int off = 16; off > 0; off >>= 1) {
            unsigned long long b1 = __shfl_down_sync(0xffffffffu, a1, off);
            unsigned long long b2 = __shfl_down_sync(0xffffffffu, a2, off);
            merge2(a1, a2, b1, b2);
        }
        if (lane == 0) { gtop[warp * 2] = a1; gtop[warp * 2 + 1] = a2; }
    }
    __syncthreads();

    if (tid == 0) {
        // sort 16 keys descending => (score desc, flat index asc) == keep order
        unsigned long long t[16];
#pragma unroll
        for (int i = 0; i < 16; ++i) t[i] = gtop[i];
        for (int i = 1; i < 16; ++i) {
            unsigned long long v = t[i];
            int j = i - 1;
            while (j >= 0 && t[j] < v) { t[j + 1] = t[j]; --j; }
            t[j + 1] = v;
        }
#pragma unroll
        for (int i = 0; i < 16; ++i) sorted16[i] = t[i];
    }
    __syncthreads();

    if (tid < 16) {
        const unsigned long long key = sorted16[tid];
        const unsigned int flat = ~((unsigned int)key);        // fg flat index
        const int prop = (int)(flat >> 1);
        const int cls  = (int)(flat & 1u) + 1;
        const float score = __uint_as_float((unsigned int)(key >> 32));
        const int b_ix = batch_ixs[prop];
        const int aidx = prop & (NA - 1);

        const float scale[6] = {256.f, 256.f, 256.f, 256.f, 128.f, 128.f};
        const float stdv[6]  = {0.1f, 0.1f, 0.1f, 0.2f, 0.2f, 0.2f};

        float anc[6], dlt[6];
#pragma unroll
        for (int j = 0; j < 6; ++j)
            anc[j] = floorf(anchors[(long long)aidx * 6 + j] / scale[j]);
#pragma unroll
        for (int j = 0; j < 6; ++j)
            dlt[j] = deltas[(long long)prop * 6 + j] * stdv[j];

        float h = anc[2] - anc[0];
        float w = anc[3] - anc[1];
        float d = anc[5] - anc[4];
        float cy = anc[0] + 0.5f * h + dlt[0] * h;
        float cx = anc[1] + 0.5f * w + dlt[1] * w;
        float cz = anc[4] + 0.5f * d + dlt[2] * d;
        h *= expf(dlt[3]);
        w *= expf(dlt[4]);
        d *= expf(dlt[5]);

        float box[6];
        box[0] = cy - 0.5f * h;
        box[1] = cx - 0.5f * w;
        box[2] = box[0] + h;
        box[3] = box[1] + w;
        box[4] = cz - 0.5f * d;
        box[5] = box[4] + d;

        float* o = out + tid * 9;
#pragma unroll
        for (int j = 0; j < 6; ++j)
            o[j] = rintf(fminf(fmaxf(box[j] * scale[j], 0.0f), scale[j]));
        o[6] = (float)b_ix;
        o[7] = (float)cls;
        o[8] = score;
    }

    // release the spinners
    __syncthreads();
    __threadfence();
    if (tid == 0) atomicAdd(&g_release, 1u);
}

extern "C" void kernel_launch(void* const* d_in, const int* in_sizes, int n_in,
                              void* d_out, int out_size) {
    // identify inputs by element count (robust to ordering)
    const float* anchors = nullptr;   // NA*6       = 6,291,456
    const float* probs   = nullptr;   // NB*NA*3    = 12,582,912
    const float* deltas  = nullptr;   // NB*NA*6    = 25,165,824
    const int* batch_ixs = nullptr;   // NB*NA      = 4,194,304
    for (int i = 0; i < n_in; ++i) {
        switch (in_sizes[i]) {
            case 6291456:  anchors   = (const float*)d_in[i]; break;
            case 12582912: probs     = (const float*)d_in[i]; break;
            case 25165824: deltas    = (const float*)d_in[i]; break;
            case 4194304:  batch_ixs = (const int*)d_in[i];   break;
            default: break;
        }
    }

    fused_top2_decode<<<NBLOCKS, NTHREADS>>>(probs, anchors, deltas, batch_ixs,
                                             (float*)d_out);
}

// round 4
// speedup vs baseline: 1.2166x; 1.2166x over previous
#include <cuda_runtime.h>
#include <cstdint>

#define NB 4
#define NA (1 << 20)
#define BPB 256                      // scan blocks per batch
#define NBLOCKS (NB * BPB)           // 1024
#define NTHREADS 256
#define ROWS_PER_BLOCK (NA / BPB)    // 4096 rows (props) per block
#define QUADS_PER_THREAD (ROWS_PER_BLOCK / 4 / NTHREADS)  // 4
#define TAIL_BLOCKS 192              // >=148 so the low-grid issue throttle never engages

// scratch: per block, 4 u64 keys: [col0_top1, col0_top2, col1_top1, col1_top2]
__device__ unsigned long long g_scratch[NBLOCKS * 4];

__device__ __forceinline__ unsigned long long make_key(float v, unsigned int idx) {
    // high 32: float bits of positive score (order-preserving for positives)
    // low 32 : ~idx  (ties in score -> smaller index = larger key)
    return (((unsigned long long)__float_as_uint(v)) << 32) | (unsigned long long)(~idx);
}

__device__ __forceinline__ void upd2(unsigned long long& a1, unsigned long long& a2,
                                     unsigned long long k) {
    if (k > a1) { a2 = a1; a1 = k; }
    else if (k > a2) { a2 = k; }
}

// merge top-2 list (b1>=b2) into (a1>=a2)
__device__ __forceinline__ void merge2(unsigned long long& a1, unsigned long long& a2,
                                       unsigned long long b1, unsigned long long b2) {
    unsigned long long hi = a1 > b1 ? a1 : b1;
    unsigned long long lo = a1 > b1 ? b1 : a1;
    unsigned long long m2 = a2 > b2 ? a2 : b2;
    a1 = hi;
    a2 = lo > m2 ? lo : m2;
}

// Pass 1 (unchanged from the proven R1 version): per-(batch,class) top-2 scan.
__global__ void __launch_bounds__(NTHREADS) pass1_top2(const float* __restrict__ probs) {
    const int blk   = blockIdx.x;
    const int batch = blk >> 8;        // / BPB
    const int chunk = blk & (BPB - 1);
    const long long row0 = (long long)batch * NA + (long long)chunk * ROWS_PER_BLOCK;
    const float4* __restrict__ p4 = reinterpret_cast<const float4*>(probs);

    unsigned long long k0a = 0, k0b = 0;  // class column 0 (cls=1)
    unsigned long long k1a = 0, k1b = 0;  // class column 1 (cls=2)

#pragma unroll
    for (int it = 0; it < QUADS_PER_THREAD; ++it) {
        const long long row = row0 + (long long)(it * NTHREADS + threadIdx.x) * 4;
        const long long f4  = (row >> 2) * 3;  // row*3/4, row % 4 == 0
        const float4 A = p4[f4];
        const float4 B = p4[f4 + 1];
        const float4 C = p4[f4 + 2];
        // A = {r0c0, r0c1, r0c2, r1c0}, B = {r1c1, r1c2, r2c0, r2c1}, C = {r2c2, r3c0, r3c1, r3c2}
        const unsigned int i0 = (unsigned int)(row * 2);  // fg flat index of (row, col0)
        upd2(k0a, k0b, make_key(A.y, i0 + 0));
        upd2(k1a, k1b, make_key(A.z, i0 + 1));
        upd2(k0a, k0b, make_key(B.x, i0 + 2));
        upd2(k1a, k1b, make_key(B.y, i0 + 3));
        upd2(k0a, k0b, make_key(B.w, i0 + 4));
        upd2(k1a, k1b, make_key(C.x, i0 + 5));
        upd2(k0a, k0b, make_key(C.z, i0 + 6));
        upd2(k1a, k1b, make_key(C.w, i0 + 7));
    }

    __shared__ unsigned long long s[NTHREADS][4];
    s[threadIdx.x][0] = k0a;
    s[threadIdx.x][1] = k0b;
    s[threadIdx.x][2] = k1a;
    s[threadIdx.x][3] = k1b;
    __syncthreads();

    for (int off = NTHREADS / 2; off > 0; off >>= 1) {
        if (threadIdx.x < off) {
            unsigned long long a1 = s[threadIdx.x][0], a2 = s[threadIdx.x][1];
            merge2(a1, a2, s[threadIdx.x + off][0], s[threadIdx.x + off][1]);
            s[threadIdx.x][0] = a1; s[threadIdx.x][1] = a2;
            unsigned long long c1 = s[threadIdx.x][2], c2 = s[threadIdx.x][3];
            merge2(c1, c2, s[threadIdx.x + off][2], s[threadIdx.x + off][3]);
            s[threadIdx.x][2] = c1; s[threadIdx.x][3] = c2;
        }
        __syncthreads();
    }

    if (threadIdx.x == 0) {
#pragma unroll
        for (int j = 0; j < 4; ++j) g_scratch[blk * 4 + j] = s[0][j];
    }
}

// Pass 2: EVERY block redundantly computes the identical final result and
// writes the same 16x9 output. With grid >= 148 the single-CTA issue-throttle
// regime never engages; the redundant L2 reads (192 x 32KB = 6MB) cost ~1us.
__global__ void __launch_bounds__(256) pass2_decode(const float* __restrict__ anchors,
                                                    const float* __restrict__ deltas,
                                                    const int* __restrict__ batch_ixs,
                                                    float* __restrict__ out) {
    __shared__ unsigned long long gtop[16];
    __shared__ unsigned long long sorted16[16];
    const int tid  = threadIdx.x;
    const int warp = tid >> 5;
    const int lane = tid & 31;

    // 8 warps, one per (batch, class) group
    {
        const int batch = warp >> 1;
        const int col   = warp & 1;
        unsigned long long a1 = 0, a2 = 0;
#pragma unroll
        for (int b = 0; b < BPB / 32; ++b) {
            const int blk = batch * BPB + b * 32 + lane;
            merge2(a1, a2, g_scratch[blk * 4 + col * 2], g_scratch[blk * 4 + col * 2 + 1]);
        }
#pragma unroll
        for (int off = 16; off > 0; off >>= 1) {
            unsigned long long b1 = __shfl_down_sync(0xffffffffu, a1, off);
            unsigned long long b2 = __shfl_down_sync(0xffffffffu, a2, off);
            merge2(a1, a2, b1, b2);
        }
        if (lane == 0) { gtop[warp * 2] = a1; gtop[warp * 2 + 1] = a2; }
    }
    __syncthreads();

    if (tid == 0) {
        // sort 16 keys descending => (score desc, flat index asc) == keep order
        unsigned long long t[16];
#pragma unroll
        for (int i = 0; i < 16; ++i) t[i] = gtop[i];
        for (int i = 1; i < 16; ++i) {
            unsigned long long v = t[i];
            int j = i - 1;
            while (j >= 0 && t[j] < v) { t[j + 1] = t[j]; --j; }
            t[j + 1] = v;
        }
#pragma unroll
        for (int i = 0; i < 16; ++i) sorted16[i] = t[i];
    }
    __syncthreads();

    if (tid < 16) {
        const unsigned long long key = sorted16[tid];
        const unsigned int flat = ~((unsigned int)key);        // fg flat index
        const int prop = (int)(flat >> 1);
        const int cls  = (int)(flat & 1u) + 1;
        const float score = __uint_as_float((unsigned int)(key >> 32));
        const int b_ix = batch_ixs[prop];
        const int aidx = prop & (NA - 1);

        const float scale[6] = {256.f, 256.f, 256.f, 256.f, 128.f, 128.f};
        const float stdv[6]  = {0.1f, 0.1f, 0.1f, 0.2f, 0.2f, 0.2f};

        float anc[6], dlt[6];
#pragma unroll
        for (int j = 0; j < 6; ++j)
            anc[j] = floorf(anchors[(long long)aidx * 6 + j] / scale[j]);
#pragma unroll
        for (int j = 0; j < 6; ++j)
            dlt[j] = deltas[(long long)prop * 6 + j] * stdv[j];

        float h = anc[2] - anc[0];
        float w = anc[3] - anc[1];
        float d = anc[5] - anc[4];
        float cy = anc[0] + 0.5f * h + dlt[0] * h;
        float cx = anc[1] + 0.5f * w + dlt[1] * w;
        float cz = anc[4] + 0.5f * d + dlt[2] * d;
        h *= expf(dlt[3]);
        w *= expf(dlt[4]);
        d *= expf(dlt[5]);

        float box[6];
        box[0] = cy - 0.5f * h;
        box[1] = cx - 0.5f * w;
        box[2] = box[0] + h;
        box[3] = box[1] + w;
        box[4] = cz - 0.5f * d;
        box[5] = box[4] + d;

        // all blocks write identical values -> benign, deterministic
        float* o = out + tid * 9;
#pragma unroll
        for (int j = 0; j < 6; ++j)
            o[j] = rintf(fminf(fmaxf(box[j] * scale[j], 0.0f), scale[j]));
        o[6] = (float)b_ix;
        o[7] = (float)cls;
        o[8] = score;
    }
}

extern "C" void kernel_launch(void* const* d_in, const int* in_sizes, int n_in,
                              void* d_out, int out_size) {
    // identify inputs by element count (robust to ordering)
    const float* anchors = nullptr;   // NA*6       = 6,291,456
    const float* probs   = nullptr;   // NB*NA*3    = 12,582,912
    const float* deltas  = nullptr;   // NB*NA*6    = 25,165,824
    const int* batch_ixs = nullptr;   // NB*NA      = 4,194,304
    for (int i = 0; i < n_in; ++i) {
        switch (in_sizes[i]) {
            case 6291456:  anchors   = (const float*)d_in[i]; break;
            case 12582912: probs     = (const float*)d_in[i]; break;
            case 25165824: deltas    = (const float*)d_in[i]; break;
            case 4194304:  batch_ixs = (const int*)d_in[i];   break;
            default: break;
        }
    }

    pass1_top2<<<NBLOCKS, NTHREADS>>>(probs);
    pass2_decode<<<TAIL_BLOCKS, 256>>>(anchors, deltas, batch_ixs, (float*)d_out);
}

// round 5
// speedup vs baseline: 1.5496x; 1.2737x over previous
#include <cuda_runtime.h>
#include <cstdint>

#define NB 4
#define NA (1 << 20)
#define BPB 256                      // scan blocks per batch
#define NBLOCKS (NB * BPB)           // 1024
#define NTHREADS 256
#define ROWS_PER_BLOCK (NA / BPB)    // 4096 rows (props) per block
#define QUADS_PER_THREAD (ROWS_PER_BLOCK / 4 / NTHREADS)  // 4

// scratch: per block, 4 u64 keys: [col0_top1, col0_top2, col1_top1, col1_top2]
__device__ unsigned long long g_scratch[NBLOCKS * 4];

__device__ __forceinline__ unsigned long long make_key(float v, unsigned int idx) {
    // high 32: float bits of positive score (order-preserving for positives)
    // low 32 : ~idx  (ties in score -> smaller index = larger key)
    return (((unsigned long long)__float_as_uint(v)) << 32) | (unsigned long long)(~idx);
}

__device__ __forceinline__ void upd2(unsigned long long& a1, unsigned long long& a2,
                                     unsigned long long k) {
    if (k > a1) { a2 = a1; a1 = k; }
    else if (k > a2) { a2 = k; }
}

// merge top-2 list (b1>=b2) into (a1>=a2)
__device__ __forceinline__ void merge2(unsigned long long& a1, unsigned long long& a2,
                                       unsigned long long b1, unsigned long long b2) {
    unsigned long long hi = a1 > b1 ? a1 : b1;
    unsigned long long lo = a1 > b1 ? b1 : a1;
    unsigned long long m2 = a2 > b2 ? a2 : b2;
    a1 = hi;
    a2 = lo > m2 ? lo : m2;
}

// Pass 1 (proven, at the LTS cap): per-(batch,class) top-2 scan.
__global__ void __launch_bounds__(NTHREADS) pass1_top2(const float* __restrict__ probs) {
    const int blk   = blockIdx.x;
    const int batch = blk >> 8;        // / BPB
    const int chunk = blk & (BPB - 1);
    const long long row0 = (long long)batch * NA + (long long)chunk * ROWS_PER_BLOCK;
    const float4* __restrict__ p4 = reinterpret_cast<const float4*>(probs);

    unsigned long long k0a = 0, k0b = 0;  // class column 0 (cls=1)
    unsigned long long k1a = 0, k1b = 0;  // class column 1 (cls=2)

#pragma unroll
    for (int it = 0; it < QUADS_PER_THREAD; ++it) {
        const long long row = row0 + (long long)(it * NTHREADS + threadIdx.x) * 4;
        const long long f4  = (row >> 2) * 3;  // row*3/4, row % 4 == 0
        const float4 A = p4[f4];
        const float4 B = p4[f4 + 1];
        const float4 C = p4[f4 + 2];
        // A = {r0c0, r0c1, r0c2, r1c0}, B = {r1c1, r1c2, r2c0, r2c1}, C = {r2c2, r3c0, r3c1, r3c2}
        const unsigned int i0 = (unsigned int)(row * 2);  // fg flat index of (row, col0)
        upd2(k0a, k0b, make_key(A.y, i0 + 0));
        upd2(k1a, k1b, make_key(A.z, i0 + 1));
        upd2(k0a, k0b, make_key(B.x, i0 + 2));
        upd2(k1a, k1b, make_key(B.y, i0 + 3));
        upd2(k0a, k0b, make_key(B.w, i0 + 4));
        upd2(k1a, k1b, make_key(C.x, i0 + 5));
        upd2(k0a, k0b, make_key(C.z, i0 + 6));
        upd2(k1a, k1b, make_key(C.w, i0 + 7));
    }

    __shared__ unsigned long long s[NTHREADS][4];
    s[threadIdx.x][0] = k0a;
    s[threadIdx.x][1] = k0b;
    s[threadIdx.x][2] = k1a;
    s[threadIdx.x][3] = k1b;
    __syncthreads();

    for (int off = NTHREADS / 2; off > 0; off >>= 1) {
        if (threadIdx.x < off) {
            unsigned long long a1 = s[threadIdx.x][0], a2 = s[threadIdx.x][1];
            merge2(a1, a2, s[threadIdx.x + off][0], s[threadIdx.x + off][1]);
            s[threadIdx.x][0] = a1; s[threadIdx.x][1] = a2;
            unsigned long long c1 = s[threadIdx.x][2], c2 = s[threadIdx.x][3];
            merge2(c1, c2, s[threadIdx.x + off][2], s[threadIdx.x + off][3]);
            s[threadIdx.x][2] = c1; s[threadIdx.x][3] = c2;
        }
        __syncthreads();
    }

    if (threadIdx.x == 0) {
#pragma unroll
        for (int j = 0; j < 4; ++j) g_scratch[blk * 4 + j] = s[0][j];
    }
}

// Pass 2: reduce scratch -> 16 keys; RANK SORT (parallel, register-only,
// no dynamic indexing -> no local-memory serial chain); decode; write 16x9.
__global__ void __launch_bounds__(256) pass2_decode(const float* __restrict__ anchors,
                                                    const float* __restrict__ deltas,
                                                    const int* __restrict__ batch_ixs,
                                                    float* __restrict__ out) {
    __shared__ unsigned long long gtop[16];
    const int tid  = threadIdx.x;
    const int warp = tid >> 5;
    const int lane = tid & 31;

    // 8 warps, one per (batch, class) group
    {
        const int batch = warp >> 1;
        const int col   = warp & 1;
        unsigned long long a1 = 0, a2 = 0;
#pragma unroll
        for (int b = 0; b < BPB / 32; ++b) {
            const int blk = batch * BPB + b * 32 + lane;
            merge2(a1, a2, g_scratch[blk * 4 + col * 2], g_scratch[blk * 4 + col * 2 + 1]);
        }
#pragma unroll
        for (int off = 16; off > 0; off >>= 1) {
            unsigned long long b1 = __shfl_down_sync(0xffffffffu, a1, off);
            unsigned long long b2 = __shfl_down_sync(0xffffffffu, a2, off);
            merge2(a1, a2, b1, b2);
        }
        if (lane == 0) { gtop[warp * 2] = a1; gtop[warp * 2 + 1] = a2; }
    }
    __syncthreads();

    if (tid < 16) {
        // rank sort: all 16 keys distinct (unique index in low bits).
        // rank = number of keys greater than mine = my descending position.
        const unsigned long long key = gtop[tid];
        int rank = 0;
#pragma unroll
        for (int j = 0; j < 16; ++j) rank += (gtop[j] > key) ? 1 : 0;

        const unsigned int flat = ~((unsigned int)key);        // fg flat index
        const int prop = (int)(flat >> 1);
        const int cls  = (int)(flat & 1u) + 1;
        const float score = __uint_as_float((unsigned int)(key >> 32));
        const int b_ix = batch_ixs[prop];
        const int aidx = prop & (NA - 1);

        const float scale[6] = {256.f, 256.f, 256.f, 256.f, 128.f, 128.f};
        const float stdv[6]  = {0.1f, 0.1f, 0.1f, 0.2f, 0.2f, 0.2f};

        float anc[6], dlt[6];
#pragma unroll
        for (int j = 0; j < 6; ++j)
            anc[j] = floorf(anchors[(long long)aidx * 6 + j] / scale[j]);
#pragma unroll
        for (int j = 0; j < 6; ++j)
            dlt[j] = deltas[(long long)prop * 6 + j] * stdv[j];

        float h = anc[2] - anc[0];
        float w = anc[3] - anc[1];
        float d = anc[5] - anc[4];
        float cy = anc[0] + 0.5f * h + dlt[0] * h;
        float cx = anc[1] + 0.5f * w + dlt[1] * w;
        float cz = anc[4] + 0.5f * d + dlt[2] * d;
        h *= expf(dlt[3]);
        w *= expf(dlt[4]);
        d *= expf(dlt[5]);

        float box[6];
        box[0] = cy - 0.5f * h;
        box[1] = cx - 0.5f * w;
        box[2] = box[0] + h;
        box[3] = box[1] + w;
        box[4] = cz - 0.5f * d;
        box[5] = box[4] + d;

        float* o = out + rank * 9;   // each thread writes its sorted slot
#pragma unroll
        for (int j = 0; j < 6; ++j)
            o[j] = rintf(fminf(fmaxf(box[j] * scale[j], 0.0f), scale[j]));
        o[6] = (float)b_ix;
        o[7] = (float)cls;
        o[8] = score;
    }
}

extern "C" void kernel_launch(void* const* d_in, const int* in_sizes, int n_in,
                              void* d_out, int out_size) {
    // identify inputs by element count (robust to ordering)
    const float* anchors = nullptr;   // NA*6       = 6,291,456
    const float* probs   = nullptr;   // NB*NA*3    = 12,582,912
    const float* deltas  = nullptr;   // NB*NA*6    = 25,165,824
    const int* batch_ixs = nullptr;   // NB*NA      = 4,194,304
    for (int i = 0; i < n_in; ++i) {
        switch (in_sizes[i]) {
            case 6291456:  anchors   = (const float*)d_in[i]; break;
            case 12582912: probs     = (const float*)d_in[i]; break;
            case 25165824: deltas    = (const float*)d_in[i]; break;
            case 4194304:  batch_ixs = (const int*)d_in[i];   break;
            default: break;
        }
    }

    pass1_top2<<<NBLOCKS, NTHREADS>>>(probs);
    pass2_decode<<<1, 256>>>(anchors, deltas, batch_ixs, (float*)d_out);
}